// round 12
// baseline (speedup 1.0000x reference)
#include <cuda_runtime.h>
#include <cuda_fp16.h>

#define N_USER 50000
#define N_ITEM 50000
#define N_EDGE 600000
#define D 128
#define NNODE 50000
#define NE4 (N_EDGE / 4)

// ---- scratch (__device__ globals) ----
__device__ int g_cnt[3][NNODE];        // zeroed by scan after use (invariant: 0 at entry)
__device__ int g_off[3][NNODE + 1];
__device__ int g_pos[3][N_EDGE];       // per-edge within-node slot (from hist atomicAdd)
__device__ int g_esrc[3][N_EDGE + 8];
__device__ uint2 g_fu_h[N_USER * (D / 4)];
__device__ uint2 g_fi_h[N_ITEM * (D / 4)];
__device__ uint2 g_agg[3][NNODE * (D / 4)];   // [0]=uu, [1]=ub, [2]=iu
__device__ __half g_Wt[3][D * D];             // [0]=W_uu, [1]=W_iu, [2]=W_ub (transposed)

// ---------------------------------------------------------------------------
__global__ void prep_kernel(const float4* __restrict__ fu, const float4* __restrict__ fi,
                            const float* __restrict__ Wuu, const float* __restrict__ Wiu,
                            const float* __restrict__ Wub) {
    int i = blockIdx.x * blockDim.x + threadIdx.x;
    const int nv = N_USER * (D / 4);
    if (i < nv) {
        float4 v = fu[i];
        __half2 h0 = __floats2half2_rn(v.x, v.y);
        __half2 h1 = __floats2half2_rn(v.z, v.w);
        uint2 o; o.x = *(unsigned*)&h0; o.y = *(unsigned*)&h1;
        g_fu_h[i] = o;
    } else if (i < 2 * nv) {
        float4 v = fi[i - nv];
        __half2 h0 = __floats2half2_rn(v.x, v.y);
        __half2 h1 = __floats2half2_rn(v.z, v.w);
        uint2 o; o.x = *(unsigned*)&h0; o.y = *(unsigned*)&h1;
        g_fi_h[i - nv] = o;
    }
    if (i < 3 * D * D) {
        int m = i >> 14;
        int r = i & (D * D - 1);
        int n = r >> 7;
        int k = r & 127;
        const float* W = (m == 0) ? Wuu : (m == 1) ? Wiu : Wub;
        g_Wt[m][(n << 7) + k] = __float2half(W[(k << 7) + n]);
    }
}

__global__ void hist_kernel(const int* __restrict__ duu, const int* __restrict__ dub,
                            const int* __restrict__ diu) {
    unsigned t = blockIdx.x * blockDim.x + threadIdx.x;
    if (t >= 3u * NE4) return;
    int type = t / NE4;
    unsigned e4 = t - (unsigned)type * NE4;
    const int* dst = (type == 0) ? duu : (type == 1) ? dub : diu;
    int4 d = ((const int4*)dst)[e4];
    int* c = g_cnt[type];
    int4 p;
    p.x = atomicAdd(c + d.x, 1);
    p.y = atomicAdd(c + d.y, 1);
    p.z = atomicAdd(c + d.z, 1);
    p.w = atomicAdd(c + d.w, 1);
    ((int4*)g_pos[type])[e4] = p;
}

// Fast scan: 1 block/relation, 1024 threads, thread-serial 2-pass, 3 barriers.
#define SCAN_C 49  // ceil(50000/1024)
__global__ __launch_bounds__(1024, 1) void scan_kernel() {
    const int type = blockIdx.x;
    const int t = threadIdx.x;
    const int lane = t & 31;
    const int wid = t >> 5;
    const int base = t * SCAN_C;

    int sum = 0;
#pragma unroll
    for (int i = 0; i < SCAN_C; i++) {
        int idx = base + i;
        if (idx < NNODE) sum += g_cnt[type][idx];
    }
    __shared__ int wsum[32];
    int x = sum;
#pragma unroll
    for (int o = 1; o < 32; o <<= 1) {
        int y = __shfl_up_sync(0xffffffffu, x, o);
        if (lane >= o) x += y;
    }
    if (lane == 31) wsum[wid] = x;
    __syncthreads();
    if (wid == 0) {
        int w = wsum[lane];
        int xs = w;
#pragma unroll
        for (int o = 1; o < 32; o <<= 1) {
            int y = __shfl_up_sync(0xffffffffu, xs, o);
            if (lane >= o) xs += y;
        }
        wsum[lane] = xs - w;
    }
    __syncthreads();
    int run = (x - sum) + wsum[wid];

    if (t == 0) g_off[type][0] = 0;
#pragma unroll
    for (int i = 0; i < SCAN_C; i++) {
        int idx = base + i;
        if (idx < NNODE) {
            int v = g_cnt[type][idx];
            g_cnt[type][idx] = 0;
            run += v;
            g_off[type][idx + 1] = run;
        }
    }
}

// atomic-free CSR fill
__global__ void fill_kernel(const int* __restrict__ suu, const int* __restrict__ duu,
                            const int* __restrict__ sub, const int* __restrict__ dub,
                            const int* __restrict__ siu, const int* __restrict__ diu) {
    unsigned t = blockIdx.x * blockDim.x + threadIdx.x;
    if (t >= 3u * NE4) return;
    int type = t / NE4;
    unsigned e4 = t - (unsigned)type * NE4;
    const int* src = (type == 0) ? suu : (type == 1) ? sub : siu;
    const int* dst = (type == 0) ? duu : (type == 1) ? dub : diu;
    int4 s = ((const int4*)src)[e4];
    int4 d = ((const int4*)dst)[e4];
    int4 p = ((const int4*)g_pos[type])[e4];
    const int* off = g_off[type];
    int* es = g_esrc[type];
    es[off[d.x] + p.x] = s.x;
    es[off[d.y] + p.y] = s.y;
    es[off[d.z] + p.z] = s.z;
    es[off[d.w] + p.w] = s.w;
}

// Single gather kernel: warp per (relation, dst-node) — R9-proven.
__global__ void gather_kernel() {
    unsigned t = blockIdx.x * blockDim.x + threadIdx.x;
    unsigned gw = t >> 5;
    int lane = threadIdx.x & 31;
    if (gw >= 3u * NNODE) return;
    int type = gw / NNODE;
    int node = gw - type * NNODE;

    const uint2* fl = ((type == 2) ? g_fi_h : g_fu_h) + lane;
    const int* es = g_esrc[type];
    int start = g_off[type][node];
    int end = g_off[type][node + 1];
    int deg = end - start;

    float4 a = make_float4(0.f, 0.f, 0.f, 0.f);
    for (int e = start; e < end; e += 4) {
        int n = end - e;
        uint2 r[4];
#pragma unroll
        for (int u = 0; u < 4; u++) {
            r[u].x = 0u; r[u].y = 0u;
            if (u < n) r[u] = fl[(unsigned)es[e + u] << 5];
        }
        __half2 tx = __hadd2(__hadd2(*(__half2*)&r[0].x, *(__half2*)&r[1].x),
                             __hadd2(*(__half2*)&r[2].x, *(__half2*)&r[3].x));
        __half2 ty = __hadd2(__hadd2(*(__half2*)&r[0].y, *(__half2*)&r[1].y),
                             __hadd2(*(__half2*)&r[2].y, *(__half2*)&r[3].y));
        float2 f0 = __half22float2(tx);
        float2 f1 = __half22float2(ty);
        a.x += f0.x; a.y += f0.y; a.z += f1.x; a.w += f1.y;
    }
    float inv = 1.0f / (float)(deg > 1 ? deg : 1);
    __half2 h0 = __floats2half2_rn(a.x * inv, a.y * inv);
    __half2 h1 = __floats2half2_rn(a.z * inv, a.w * inv);
    uint2 o; o.x = *(unsigned*)&h0; o.y = *(unsigned*)&h1;
    g_agg[type][(unsigned)node * 32u + (unsigned)lane] = o;
}

// ---------------------------------------------------------------------------
// HMMA GEMM — R9-proven: single merged launch, BM=64, static smem.
// blocks [0,BU): out_user = agg_uu@Wt0 + agg_iu@Wt1 + masked b_uu/b_iu
// blocks [BU,..): out_item = agg_ub@Wt2 + masked b_ub
__global__ void gemm_hmma_kernel(const float* __restrict__ b_uu,
                                 const float* __restrict__ b_iu,
                                 const float* __restrict__ b_ub,
                                 float* __restrict__ out, int BU) {
    __shared__ __align__(16) __half sA[64 * 128];
    __shared__ __align__(16) __half sB[128 * 128];

    int mode, bx;
    if ((int)blockIdx.x < BU) { mode = 0; bx = blockIdx.x; }
    else { mode = 1; bx = blockIdx.x - BU; }
    const int m0 = bx * 64;

    const int tid = threadIdx.x;
    const int wid = tid >> 5;
    const int lane = tid & 31;
    const int g = lane >> 2;
    const int tq = lane & 3;
    const int wr = (wid & 1) * 32;
    const int wc = (wid >> 1) * 32;

    float dacc[2][4][4];
#pragma unroll
    for (int mt = 0; mt < 2; mt++)
#pragma unroll
        for (int nt = 0; nt < 4; nt++)
#pragma unroll
            for (int q = 0; q < 4; q++) dacc[mt][nt][q] = 0.f;

    const int nsrc = (mode == 0) ? 2 : 1;
    for (int s = 0; s < nsrc; s++) {
        const uint2* A = (mode == 0) ? (s ? g_agg[2] : g_agg[0]) : g_agg[1];
        const __half* Wt = (mode == 0) ? (s ? g_Wt[1] : g_Wt[0]) : g_Wt[2];

        if (s) __syncthreads();
#pragma unroll
        for (int it = 0; it < 4; it++) {
            int idx = it * 256 + tid;
            int r = idx >> 4;
            int c16 = idx & 15;
            int grow = m0 + r;
            uint4 v = make_uint4(0u, 0u, 0u, 0u);
            if (grow < NNODE) v = ((const uint4*)(A + (size_t)grow * 32))[c16];
            *(uint4*)((char*)sA + r * 256 + ((c16 ^ (r & 7)) * 16)) = v;
        }
#pragma unroll
        for (int it = 0; it < 8; it++) {
            int idx = it * 256 + tid;
            int r = idx >> 4;
            int c16 = idx & 15;
            uint4 v = ((const uint4*)Wt)[idx];
            *(uint4*)((char*)sB + r * 256 + ((c16 ^ (r & 7)) * 16)) = v;
        }
        __syncthreads();

#pragma unroll
        for (int ks = 0; ks < 8; ks++) {
            const int k0 = ks * 16;
            unsigned a[2][4];
#pragma unroll
            for (int mt = 0; mt < 2; mt++) {
                int r0 = wr + mt * 16 + g;
                int r1 = r0 + 8;
                int w0 = (k0 >> 1) + tq;
                int w1 = w0 + 4;
                a[mt][0] = *(unsigned*)((char*)sA + r0 * 256 + ((w0 ^ ((r0 & 7) << 2)) << 2));
                a[mt][1] = *(unsigned*)((char*)sA + r1 * 256 + ((w0 ^ ((r1 & 7) << 2)) << 2));
                a[mt][2] = *(unsigned*)((char*)sA + r0 * 256 + ((w1 ^ ((r0 & 7) << 2)) << 2));
                a[mt][3] = *(unsigned*)((char*)sA + r1 * 256 + ((w1 ^ ((r1 & 7) << 2)) << 2));
            }
#pragma unroll
            for (int nt = 0; nt < 4; nt++) {
                int n = wc + nt * 8 + g;
                int w0 = (k0 >> 1) + tq;
                int w1 = w0 + 4;
                unsigned b0 = *(unsigned*)((char*)sB + n * 256 + ((w0 ^ ((n & 7) << 2)) << 2));
                unsigned b1 = *(unsigned*)((char*)sB + n * 256 + ((w1 ^ ((n & 7) << 2)) << 2));
#pragma unroll
                for (int mt = 0; mt < 2; mt++) {
                    asm volatile(
                        "mma.sync.aligned.m16n8k16.row.col.f32.f16.f16.f32 "
                        "{%0,%1,%2,%3}, {%4,%5,%6,%7}, {%8,%9}, {%0,%1,%2,%3};"
                        : "+f"(dacc[mt][nt][0]), "+f"(dacc[mt][nt][1]),
                          "+f"(dacc[mt][nt][2]), "+f"(dacc[mt][nt][3])
                        : "r"(a[mt][0]), "r"(a[mt][1]), "r"(a[mt][2]), "r"(a[mt][3]),
                          "r"(b0), "r"(b1));
                }
            }
        }
    }

    float* outp = (mode == 0) ? out : out + (size_t)N_USER * D;
    const float* bias1 = (mode == 0) ? b_uu : b_ub;
    const int* off1 = (mode == 0) ? g_off[0] : g_off[1];
    const int* off2 = g_off[2];

    float2 bv1[4], bv2[4];
#pragma unroll
    for (int nt = 0; nt < 4; nt++) {
        int col = wc + nt * 8 + tq * 2;
        bv1[nt] = *(const float2*)(bias1 + col);
        bv2[nt] = (mode == 0) ? *(const float2*)(b_iu + col) : make_float2(0.f, 0.f);
    }

#pragma unroll
    for (int mt = 0; mt < 2; mt++) {
#pragma unroll
        for (int half_m = 0; half_m < 2; half_m++) {
            int row = m0 + wr + mt * 16 + half_m * 8 + g;
            if (row >= NNODE) continue;
            bool m1 = off1[row + 1] > off1[row];
            bool m2 = (mode == 0) && (off2[row + 1] > off2[row]);
#pragma unroll
            for (int nt = 0; nt < 4; nt++) {
                int col = wc + nt * 8 + tq * 2;
                float2 v;
                v.x = dacc[mt][nt][half_m * 2 + 0];
                v.y = dacc[mt][nt][half_m * 2 + 1];
                if (m1) { v.x += bv1[nt].x; v.y += bv1[nt].y; }
                if (m2) { v.x += bv2[nt].x; v.y += bv2[nt].y; }
                *(float2*)(outp + (size_t)row * D + col) = v;
            }
        }
    }
}

extern "C" void kernel_launch(void* const* d_in, const int* in_sizes, int n_in,
                              void* d_out, int out_size) {
    const float* feat_user = (const float*)d_in[0];
    const float* feat_item = (const float*)d_in[1];
    const float* W_uu = (const float*)d_in[2];
    const float* b_uu = (const float*)d_in[3];
    const float* W_ub = (const float*)d_in[4];
    const float* b_ub = (const float*)d_in[5];
    const float* W_iu = (const float*)d_in[6];
    const float* b_iu = (const float*)d_in[7];
    const int* src_uu = (const int*)d_in[8];
    const int* dst_uu = (const int*)d_in[9];
    const int* src_ub = (const int*)d_in[10];
    const int* dst_ub = (const int*)d_in[11];
    const int* src_iu = (const int*)d_in[12];
    const int* dst_iu = (const int*)d_in[13];
    float* out = (float*)d_out;

    static cudaStream_t s2 = nullptr;
    static cudaEvent_t e_root = nullptr, e_prep = nullptr;
    if (!s2) {
        cudaStreamCreate(&s2);
        cudaEventCreateWithFlags(&e_root, cudaEventDisableTiming);
        cudaEventCreateWithFlags(&e_prep, cudaEventDisableTiming);
    }

    // fork: fp16 conversion concurrent with CSR build (R9-proven)
    cudaEventRecord(e_root, 0);
    cudaStreamWaitEvent(s2, e_root, 0);
    int prep_threads = 2 * N_USER * (D / 4);
    prep_kernel<<<(prep_threads + 255) / 256, 256, 0, s2>>>(
        (const float4*)feat_user, (const float4*)feat_item, W_uu, W_iu, W_ub);
    cudaEventRecord(e_prep, s2);

    // main stream: CSR build
    hist_kernel<<<(3 * NE4 + 255) / 256, 256>>>(dst_uu, dst_ub, dst_iu);
    scan_kernel<<<3, 1024>>>();
    fill_kernel<<<(3 * NE4 + 255) / 256, 256>>>(src_uu, dst_uu, src_ub, dst_ub,
                                                src_iu, dst_iu);

    // join prep; single full gather; single merged GEMM
    cudaStreamWaitEvent(0, e_prep, 0);
    unsigned gthreads = 3u * NNODE * 32u;
    gather_kernel<<<(gthreads + 255) / 256, 256>>>();

    int BU = (N_USER + 63) / 64;
    int BI = (N_ITEM + 63) / 64;
    gemm_hmma_kernel<<<BU + BI, 256>>>(b_uu, b_iu, b_ub, out, BU);
}

// round 13
// speedup vs baseline: 1.3858x; 1.3858x over previous
#include <cuda_runtime.h>
#include <cuda_fp16.h>

#define N_USER 50000
#define N_ITEM 50000
#define N_EDGE 600000
#define D 128
#define NNODE 50000
#define NE4 (N_EDGE / 4)

// ---- scratch (__device__ globals) ----
__device__ int g_cnt[3][NNODE];        // zeroed by scan after use (invariant: 0 at entry)
__device__ int g_off[3][NNODE + 1];
__device__ int g_pos[3][N_EDGE];       // per-edge within-node slot (from hist atomicAdd)
__device__ int g_esrc[3][N_EDGE + 8];
__device__ uint2 g_fu_h[N_USER * (D / 4)];
__device__ uint2 g_fi_h[N_ITEM * (D / 4)];
__device__ uint2 g_agg[3][NNODE * (D / 4)];   // [0]=uu, [1]=ub, [2]=iu
__device__ __half g_Wt[3][D * D];             // [0]=W_uu, [1]=W_iu, [2]=W_ub (transposed)

// ---------------------------------------------------------------------------
__global__ void prep_kernel(const float4* __restrict__ fu, const float4* __restrict__ fi,
                            const float* __restrict__ Wuu, const float* __restrict__ Wiu,
                            const float* __restrict__ Wub) {
    int i = blockIdx.x * blockDim.x + threadIdx.x;
    const int nv = N_USER * (D / 4);
    if (i < nv) {
        float4 v = fu[i];
        __half2 h0 = __floats2half2_rn(v.x, v.y);
        __half2 h1 = __floats2half2_rn(v.z, v.w);
        uint2 o; o.x = *(unsigned*)&h0; o.y = *(unsigned*)&h1;
        g_fu_h[i] = o;
    } else if (i < 2 * nv) {
        float4 v = fi[i - nv];
        __half2 h0 = __floats2half2_rn(v.x, v.y);
        __half2 h1 = __floats2half2_rn(v.z, v.w);
        uint2 o; o.x = *(unsigned*)&h0; o.y = *(unsigned*)&h1;
        g_fi_h[i - nv] = o;
    }
    if (i < 3 * D * D) {
        int m = i >> 14;
        int r = i & (D * D - 1);
        int n = r >> 7;
        int k = r & 127;
        const float* W = (m == 0) ? Wuu : (m == 1) ? Wiu : Wub;
        g_Wt[m][(n << 7) + k] = __float2half(W[(k << 7) + n]);
    }
}

__global__ void hist_kernel(const int* __restrict__ duu, const int* __restrict__ dub,
                            const int* __restrict__ diu) {
    unsigned t = blockIdx.x * blockDim.x + threadIdx.x;
    if (t >= 3u * NE4) return;
    int type = t / NE4;
    unsigned e4 = t - (unsigned)type * NE4;
    const int* dst = (type == 0) ? duu : (type == 1) ? dub : diu;
    int4 d = ((const int4*)dst)[e4];
    int* c = g_cnt[type];
    int4 p;
    p.x = atomicAdd(c + d.x, 1);
    p.y = atomicAdd(c + d.y, 1);
    p.z = atomicAdd(c + d.z, 1);
    p.w = atomicAdd(c + d.w, 1);
    ((int4*)g_pos[type])[e4] = p;
}

// Coalesced low-barrier scan: 1 block/relation, 1024 threads.
// Each thread owns 4 CONSECUTIVE elements via one int4 load (warp reads 512
// contiguous bytes -> fully coalesced). Chunk = 4096 elems; 13 chunks;
// 4 barriers per chunk. Also re-zeroes g_cnt.
#define N_INT4 (NNODE / 4)  // 12500
__global__ __launch_bounds__(1024, 1) void scan_kernel() {
    const int type = blockIdx.x;
    const int t = threadIdx.x;
    const int lane = t & 31;
    const int wid = t >> 5;
    __shared__ int wsum[32];
    __shared__ int s_total;
    __shared__ int s_carry;
    if (t == 0) { s_carry = 0; g_off[type][0] = 0; }
    __syncthreads();

    int4* cnt4 = (int4*)g_cnt[type];
    int* off = g_off[type];

    for (int c = 0; c < (N_INT4 + 1023) / 1024; c++) {
        int i4 = c * 1024 + t;
        bool ok = i4 < N_INT4;
        int4 v = make_int4(0, 0, 0, 0);
        if (ok) {
            v = cnt4[i4];                       // coalesced 16B/lane
            cnt4[i4] = make_int4(0, 0, 0, 0);   // restore invariant
        }
        int tsum = v.x + v.y + v.z + v.w;
        // warp inclusive scan of per-thread sums
        int x = tsum;
#pragma unroll
        for (int o = 1; o < 32; o <<= 1) {
            int y = __shfl_up_sync(0xffffffffu, x, o);
            if (lane >= o) x += y;
        }
        if (lane == 31) wsum[wid] = x;
        __syncthreads();
        if (wid == 0) {
            int w = wsum[lane];
            int xs = w;
#pragma unroll
            for (int o = 1; o < 32; o <<= 1) {
                int y = __shfl_up_sync(0xffffffffu, xs, o);
                if (lane >= o) xs += y;
            }
            wsum[lane] = xs - w;                // exclusive warp offsets
            if (lane == 31) s_total = xs;       // chunk total
        }
        __syncthreads();
        int run = s_carry + (x - tsum) + wsum[wid];  // exclusive prefix for this thread
        if (ok) {
            int idx = i4 * 4;
            run += v.x; off[idx + 1] = run;
            run += v.y; off[idx + 2] = run;
            run += v.z; off[idx + 3] = run;
            run += v.w; off[idx + 4] = run;
        }
        __syncthreads();                        // everyone has read s_carry
        if (t == 0) s_carry += s_total;
        __syncthreads();
    }
}

// atomic-free CSR fill
__global__ void fill_kernel(const int* __restrict__ suu, const int* __restrict__ duu,
                            const int* __restrict__ sub, const int* __restrict__ dub,
                            const int* __restrict__ siu, const int* __restrict__ diu) {
    unsigned t = blockIdx.x * blockDim.x + threadIdx.x;
    if (t >= 3u * NE4) return;
    int type = t / NE4;
    unsigned e4 = t - (unsigned)type * NE4;
    const int* src = (type == 0) ? suu : (type == 1) ? sub : siu;
    const int* dst = (type == 0) ? duu : (type == 1) ? dub : diu;
    int4 s = ((const int4*)src)[e4];
    int4 d = ((const int4*)dst)[e4];
    int4 p = ((const int4*)g_pos[type])[e4];
    const int* off = g_off[type];
    int* es = g_esrc[type];
    es[off[d.x] + p.x] = s.x;
    es[off[d.y] + p.y] = s.y;
    es[off[d.z] + p.z] = s.z;
    es[off[d.w] + p.w] = s.w;
}

// Single gather kernel: warp per (relation, dst-node) — R9-proven.
__global__ void gather_kernel() {
    unsigned t = blockIdx.x * blockDim.x + threadIdx.x;
    unsigned gw = t >> 5;
    int lane = threadIdx.x & 31;
    if (gw >= 3u * NNODE) return;
    int type = gw / NNODE;
    int node = gw - type * NNODE;

    const uint2* fl = ((type == 2) ? g_fi_h : g_fu_h) + lane;
    const int* es = g_esrc[type];
    int start = g_off[type][node];
    int end = g_off[type][node + 1];
    int deg = end - start;

    float4 a = make_float4(0.f, 0.f, 0.f, 0.f);
    for (int e = start; e < end; e += 4) {
        int n = end - e;
        uint2 r[4];
#pragma unroll
        for (int u = 0; u < 4; u++) {
            r[u].x = 0u; r[u].y = 0u;
            if (u < n) r[u] = fl[(unsigned)es[e + u] << 5];
        }
        __half2 tx = __hadd2(__hadd2(*(__half2*)&r[0].x, *(__half2*)&r[1].x),
                             __hadd2(*(__half2*)&r[2].x, *(__half2*)&r[3].x));
        __half2 ty = __hadd2(__hadd2(*(__half2*)&r[0].y, *(__half2*)&r[1].y),
                             __hadd2(*(__half2*)&r[2].y, *(__half2*)&r[3].y));
        float2 f0 = __half22float2(tx);
        float2 f1 = __half22float2(ty);
        a.x += f0.x; a.y += f0.y; a.z += f1.x; a.w += f1.y;
    }
    float inv = 1.0f / (float)(deg > 1 ? deg : 1);
    __half2 h0 = __floats2half2_rn(a.x * inv, a.y * inv);
    __half2 h1 = __floats2half2_rn(a.z * inv, a.w * inv);
    uint2 o; o.x = *(unsigned*)&h0; o.y = *(unsigned*)&h1;
    g_agg[type][(unsigned)node * 32u + (unsigned)lane] = o;
}

// ---------------------------------------------------------------------------
// HMMA GEMM — R9-proven: single merged launch, BM=64, static smem.
__global__ void gemm_hmma_kernel(const float* __restrict__ b_uu,
                                 const float* __restrict__ b_iu,
                                 const float* __restrict__ b_ub,
                                 float* __restrict__ out, int BU) {
    __shared__ __align__(16) __half sA[64 * 128];
    __shared__ __align__(16) __half sB[128 * 128];

    int mode, bx;
    if ((int)blockIdx.x < BU) { mode = 0; bx = blockIdx.x; }
    else { mode = 1; bx = blockIdx.x - BU; }
    const int m0 = bx * 64;

    const int tid = threadIdx.x;
    const int wid = tid >> 5;
    const int lane = tid & 31;
    const int g = lane >> 2;
    const int tq = lane & 3;
    const int wr = (wid & 1) * 32;
    const int wc = (wid >> 1) * 32;

    float dacc[2][4][4];
#pragma unroll
    for (int mt = 0; mt < 2; mt++)
#pragma unroll
        for (int nt = 0; nt < 4; nt++)
#pragma unroll
            for (int q = 0; q < 4; q++) dacc[mt][nt][q] = 0.f;

    const int nsrc = (mode == 0) ? 2 : 1;
    for (int s = 0; s < nsrc; s++) {
        const uint2* A = (mode == 0) ? (s ? g_agg[2] : g_agg[0]) : g_agg[1];
        const __half* Wt = (mode == 0) ? (s ? g_Wt[1] : g_Wt[0]) : g_Wt[2];

        if (s) __syncthreads();
#pragma unroll
        for (int it = 0; it < 4; it++) {
            int idx = it * 256 + tid;
            int r = idx >> 4;
            int c16 = idx & 15;
            int grow = m0 + r;
            uint4 v = make_uint4(0u, 0u, 0u, 0u);
            if (grow < NNODE) v = ((const uint4*)(A + (size_t)grow * 32))[c16];
            *(uint4*)((char*)sA + r * 256 + ((c16 ^ (r & 7)) * 16)) = v;
        }
#pragma unroll
        for (int it = 0; it < 8; it++) {
            int idx = it * 256 + tid;
            int r = idx >> 4;
            int c16 = idx & 15;
            uint4 v = ((const uint4*)Wt)[idx];
            *(uint4*)((char*)sB + r * 256 + ((c16 ^ (r & 7)) * 16)) = v;
        }
        __syncthreads();

#pragma unroll
        for (int ks = 0; ks < 8; ks++) {
            const int k0 = ks * 16;
            unsigned a[2][4];
#pragma unroll
            for (int mt = 0; mt < 2; mt++) {
                int r0 = wr + mt * 16 + g;
                int r1 = r0 + 8;
                int w0 = (k0 >> 1) + tq;
                int w1 = w0 + 4;
                a[mt][0] = *(unsigned*)((char*)sA + r0 * 256 + ((w0 ^ ((r0 & 7) << 2)) << 2));
                a[mt][1] = *(unsigned*)((char*)sA + r1 * 256 + ((w0 ^ ((r1 & 7) << 2)) << 2));
                a[mt][2] = *(unsigned*)((char*)sA + r0 * 256 + ((w1 ^ ((r0 & 7) << 2)) << 2));
                a[mt][3] = *(unsigned*)((char*)sA + r1 * 256 + ((w1 ^ ((r1 & 7) << 2)) << 2));
            }
#pragma unroll
            for (int nt = 0; nt < 4; nt++) {
                int n = wc + nt * 8 + g;
                int w0 = (k0 >> 1) + tq;
                int w1 = w0 + 4;
                unsigned b0 = *(unsigned*)((char*)sB + n * 256 + ((w0 ^ ((n & 7) << 2)) << 2));
                unsigned b1 = *(unsigned*)((char*)sB + n * 256 + ((w1 ^ ((n & 7) << 2)) << 2));
#pragma unroll
                for (int mt = 0; mt < 2; mt++) {
                    asm volatile(
                        "mma.sync.aligned.m16n8k16.row.col.f32.f16.f16.f32 "
                        "{%0,%1,%2,%3}, {%4,%5,%6,%7}, {%8,%9}, {%0,%1,%2,%3};"
                        : "+f"(dacc[mt][nt][0]), "+f"(dacc[mt][nt][1]),
                          "+f"(dacc[mt][nt][2]), "+f"(dacc[mt][nt][3])
                        : "r"(a[mt][0]), "r"(a[mt][1]), "r"(a[mt][2]), "r"(a[mt][3]),
                          "r"(b0), "r"(b1));
                }
            }
        }
    }

    float* outp = (mode == 0) ? out : out + (size_t)N_USER * D;
    const float* bias1 = (mode == 0) ? b_uu : b_ub;
    const int* off1 = (mode == 0) ? g_off[0] : g_off[1];
    const int* off2 = g_off[2];

    float2 bv1[4], bv2[4];
#pragma unroll
    for (int nt = 0; nt < 4; nt++) {
        int col = wc + nt * 8 + tq * 2;
        bv1[nt] = *(const float2*)(bias1 + col);
        bv2[nt] = (mode == 0) ? *(const float2*)(b_iu + col) : make_float2(0.f, 0.f);
    }

#pragma unroll
    for (int mt = 0; mt < 2; mt++) {
#pragma unroll
        for (int half_m = 0; half_m < 2; half_m++) {
            int row = m0 + wr + mt * 16 + half_m * 8 + g;
            if (row >= NNODE) continue;
            bool m1 = off1[row + 1] > off1[row];
            bool m2 = (mode == 0) && (off2[row + 1] > off2[row]);
#pragma unroll
            for (int nt = 0; nt < 4; nt++) {
                int col = wc + nt * 8 + tq * 2;
                float2 v;
                v.x = dacc[mt][nt][half_m * 2 + 0];
                v.y = dacc[mt][nt][half_m * 2 + 1];
                if (m1) { v.x += bv1[nt].x; v.y += bv1[nt].y; }
                if (m2) { v.x += bv2[nt].x; v.y += bv2[nt].y; }
                *(float2*)(outp + (size_t)row * D + col) = v;
            }
        }
    }
}

extern "C" void kernel_launch(void* const* d_in, const int* in_sizes, int n_in,
                              void* d_out, int out_size) {
    const float* feat_user = (const float*)d_in[0];
    const float* feat_item = (const float*)d_in[1];
    const float* W_uu = (const float*)d_in[2];
    const float* b_uu = (const float*)d_in[3];
    const float* W_ub = (const float*)d_in[4];
    const float* b_ub = (const float*)d_in[5];
    const float* W_iu = (const float*)d_in[6];
    const float* b_iu = (const float*)d_in[7];
    const int* src_uu = (const int*)d_in[8];
    const int* dst_uu = (const int*)d_in[9];
    const int* src_ub = (const int*)d_in[10];
    const int* dst_ub = (const int*)d_in[11];
    const int* src_iu = (const int*)d_in[12];
    const int* dst_iu = (const int*)d_in[13];
    float* out = (float*)d_out;

    static cudaStream_t s2 = nullptr;
    static cudaEvent_t e_root = nullptr, e_prep = nullptr;
    if (!s2) {
        cudaStreamCreate(&s2);
        cudaEventCreateWithFlags(&e_root, cudaEventDisableTiming);
        cudaEventCreateWithFlags(&e_prep, cudaEventDisableTiming);
    }

    // fork: fp16 conversion concurrent with CSR build (R9-proven)
    cudaEventRecord(e_root, 0);
    cudaStreamWaitEvent(s2, e_root, 0);
    int prep_threads = 2 * N_USER * (D / 4);
    prep_kernel<<<(prep_threads + 255) / 256, 256, 0, s2>>>(
        (const float4*)feat_user, (const float4*)feat_item, W_uu, W_iu, W_ub);
    cudaEventRecord(e_prep, s2);

    // main stream: CSR build
    hist_kernel<<<(3 * NE4 + 255) / 256, 256>>>(dst_uu, dst_ub, dst_iu);
    scan_kernel<<<3, 1024>>>();
    fill_kernel<<<(3 * NE4 + 255) / 256, 256>>>(src_uu, dst_uu, src_ub, dst_ub,
                                                src_iu, dst_iu);

    // join prep; single full gather; single merged GEMM
    cudaStreamWaitEvent(0, e_prep, 0);
    unsigned gthreads = 3u * NNODE * 32u;
    gather_kernel<<<(gthreads + 255) / 256, 256>>>();

    int BU = (N_USER + 63) / 64;
    int BI = (N_ITEM + 63) / 64;
    gemm_hmma_kernel<<<BU + BI, 256>>>(b_uu, b_iu, b_ub, out, BU);
}